// round 4
// baseline (speedup 1.0000x reference)
#include <cuda_runtime.h>

typedef unsigned long long ull;

#define B_   4
#define C_   64
#define H_   96
#define W_   96
#define DD   8
#define HW   (H_*W_)          // 9216
#define HWD  (H_*W_*DD)       // 73728
#define NIDX 243

#define PX   32
#define PT   8
#define CCH  8
#define NST  72      // 9 i-shifts * 8 channel chunks
#define F1COL 36     // stride/4 odd -> perfect 4-phase LDS.128
#define F2COL 44
#define F1W  (CCH*8*F1COL)     // 2304 words
#define F2W  (CCH*10*F2COL)    // 3520 words
#define SMEM_WORDS (2*F1W + 2*F2W)
#define SMEM_BYTES (SMEM_WORDS*4)   // 46592 B

__device__ float g_m1[B_*HW];
__device__ float g_m2[B_*HW];

__device__ __forceinline__ void fma2(ull &d, ull a, ull b) {
    asm("fma.rn.f32x2 %0, %1, %2, %0;" : "+l"(d) : "l"(a), "l"(b));
}
__device__ __forceinline__ ull mul2(ull a, ull b) {
    ull d; asm("mul.rn.f32x2 %0, %1, %2;" : "=l"(d) : "l"(a), "l"(b)); return d;
}
__device__ __forceinline__ ull pack2(float lo, float hi) {
    ull r; asm("mov.b64 %0, {%1, %2};" : "=l"(r) : "f"(lo), "f"(hi)); return r;
}
__device__ __forceinline__ void unpack2(ull v, float &lo, float &hi) {
    asm("mov.b64 {%0, %1}, %2;" : "=f"(lo), "=f"(hi) : "l"(v));
}

// ---------------------------------------------------------------------------
// Producer-warp stage fill (lane = 0..31). Two-phase: batch LDG.128 into
// registers (MLP ~24), then batch STS.32 (conflict-free: q halves occupy
// complementary bank sets). f1: 512 float4 slots, f2: 672 (exact multiples).
// ---------------------------------------------------------------------------
__device__ __forceinline__ void fill_stage_p(
    float* __restrict__ f1d, float* __restrict__ f2d,
    const float* __restrict__ f1g, const float* __restrict__ f2g,
    int b, int y, int xb, int i, int cc, int lane)
{
    const int cbase = cc * CCH;
    const float* s1 = f1g + (((size_t)(b*C_ + cbase)*H_ + y)*W_ + xb) * DD;

    const int yr = y + i - 4;
    const bool vrow = (yr >= 0) && (yr < H_);
    const float* s2 = f2g + ((size_t)(b*C_ + cbase)*H_ + (vrow ? yr : 0)) * (size_t)(W_*DD);

    // ---- phase A loads: all 16 f1 float4 + first 8 f2 float4
    float4 A[16];
    #pragma unroll
    for (int it = 0; it < 16; it++) {
        unsigned idx = lane + it*32;
        unsigned c = idx >> 6, r = idx & 63, col = r >> 1, q = r & 1;
        A[it] = *(const float4*)(s1 + (size_t)c*HWD + col*DD + q*4);
    }
    float4 Bv[8];
    #pragma unroll
    for (int it = 0; it < 8; it++) {
        unsigned idx = lane + it*32;
        unsigned cl = idx / 84u, r = idx - cl*84u, col = r >> 1, q = r & 1;
        int gx = xb - 4 + (int)col;
        float4 v = make_float4(0.f,0.f,0.f,0.f);
        if (vrow && gx >= 0 && gx < W_)
            v = *(const float4*)(s2 + (size_t)cl*HWD + gx*DD + q*4);
        Bv[it] = v;
    }
    // ---- store f1
    #pragma unroll
    for (int it = 0; it < 16; it++) {
        unsigned idx = lane + it*32;
        unsigned c = idx >> 6, r = idx & 63, col = r >> 1, q = r & 1;
        int wb = (c*8 + q*4)*F1COL + col;
        f1d[wb]          = A[it].x;
        f1d[wb+F1COL]    = A[it].y;
        f1d[wb+2*F1COL]  = A[it].z;
        f1d[wb+3*F1COL]  = A[it].w;
    }
    // ---- load remaining 13 f2 float4
    float4 Cv[13];
    #pragma unroll
    for (int it = 0; it < 13; it++) {
        unsigned idx = lane + (it+8)*32;
        unsigned cl = idx / 84u, r = idx - cl*84u, col = r >> 1, q = r & 1;
        int gx = xb - 4 + (int)col;
        float4 v = make_float4(0.f,0.f,0.f,0.f);
        if (vrow && gx >= 0 && gx < W_)
            v = *(const float4*)(s2 + (size_t)cl*HWD + gx*DD + q*4);
        Cv[it] = v;
    }
    // ---- store f2 batch B then C
    #pragma unroll
    for (int it = 0; it < 8; it++) {
        unsigned idx = lane + it*32;
        unsigned cl = idx / 84u, r = idx - cl*84u, col = r >> 1, q = r & 1;
        int wb = ((int)cl*10 + 1 + (int)q*4)*F2COL + (int)col;
        f2d[wb]          = Bv[it].x;
        f2d[wb+F2COL]    = Bv[it].y;
        f2d[wb+2*F2COL]  = Bv[it].z;
        f2d[wb+3*F2COL]  = Bv[it].w;
    }
    #pragma unroll
    for (int it = 0; it < 13; it++) {
        unsigned idx = lane + (it+8)*32;
        unsigned cl = idx / 84u, r = idx - cl*84u, col = r >> 1, q = r & 1;
        int wb = ((int)cl*10 + 1 + (int)q*4)*F2COL + (int)col;
        f2d[wb]          = Cv[it].x;
        f2d[wb+F2COL]    = Cv[it].y;
        f2d[wb+2*F2COL]  = Cv[it].z;
        f2d[wb+3*F2COL]  = Cv[it].w;
    }
}

// ---------------------------------------------------------------------------
// Warp-specialized cost + mask kernel. 128 threads: warps 0-2 compute
// (txg4 x z8, k = warp id), warp 3 = producer (all fills). Compute warps run
// pure LDS.128 + fma.f32x2 between barriers — no exposed LDG latency.
// ---------------------------------------------------------------------------
__global__ void __launch_bounds__(128, 3)
cost_kernel(const float* __restrict__ f1g, const float* __restrict__ f2g,
            float* __restrict__ out, float* __restrict__ omask)
{
    extern __shared__ float sm[];
    float* f1b0 = sm;
    float* f1b1 = sm + F1W;
    float* f2b0 = sm + 2*F1W;
    float* f2b1 = sm + 2*F1W + F2W;

    const int tid = threadIdx.x;
    const int xb  = blockIdx.x * PX;
    const int y   = blockIdx.y;
    const int b   = blockIdx.z;
    const bool producer = (tid >= 96);

    // compute-thread coords
    const int txg = tid & 3;
    const int z   = (tid >> 2) & 7;
    const int k   = tid >> 5;            // 0..2 for compute warps
    const int lx0 = txg * PT;
    const int zi  = z + k;               // 0..9

    // zero f2 z-pad planes (all threads, once)
    for (int n = tid; n < 2*CCH*2*F2COL; n += 128) {
        int p   = n / (CCH*2*F2COL);
        int r   = n - p*(CCH*2*F2COL);
        int cl  = r / (2*F2COL);
        int r2  = r - cl*(2*F2COL);
        int zp  = (r2 >= F2COL) ? 9 : 0;
        int col = (r2 >= F2COL) ? (r2 - F2COL) : r2;
        (p ? f2b1 : f2b0)[(cl*10 + zp)*F2COL + col] = 0.f;
    }
    __syncthreads();

    float m1x[PT];
    ull acc[4][9];

    if (producer) {
        fill_stage_p(f1b0, f2b0, f1g, f2g, b, y, xb, 0, 0, tid - 96);
    } else {
        const float* m1p = g_m1 + b*HW + y*W_ + xb + lx0;
        float4 a = *(const float4*)(m1p);
        float4 c = *(const float4*)(m1p + 4);
        m1x[0]=a.x; m1x[1]=a.y; m1x[2]=a.z; m1x[3]=a.w;
        m1x[4]=c.x; m1x[5]=c.y; m1x[6]=c.z; m1x[7]=c.w;
    }
    const bool zedge = (zi == 0) || (zi == 9);

    for (int s = 0; s < NST; s++) {
        const int par = s & 1;
        __syncthreads();   // fill of buf[par] done; prior use of buf[par^1] done

        if (producer) {
            if (s + 1 < NST)
                fill_stage_p(par ? f1b0 : f1b1, par ? f2b0 : f2b1,
                             f1g, f2g, b, y, xb, (s+1) >> 3, (s+1) & 7, tid - 96);
            continue;
        }

        const int i  = s >> 3;
        const int cc = s & 7;

        if (cc == 0) {
            #pragma unroll
            for (int xp = 0; xp < 4; xp++)
                #pragma unroll
                for (int j = 0; j < 9; j++) acc[xp][j] = 0ull;
        }

        const float* f1s = par ? f1b1 : f1b0;
        const float* f2s = par ? f2b1 : f2b0;

        #pragma unroll 4
        for (int cl = 0; cl < CCH; cl++) {
            const float4* p1 = (const float4*)(f1s + (cl*8 + z)*F1COL + lx0);
            float4 va = p1[0], vb = p1[1];
            ull vp[4];
            vp[0] = pack2(va.x, va.y); vp[1] = pack2(va.z, va.w);
            vp[2] = pack2(vb.x, vb.y); vp[3] = pack2(vb.z, vb.w);

            const float4* p2 = (const float4*)(f2s + (cl*10 + zi)*F2COL + lx0);
            float4 t0 = p2[0], t1 = p2[1], t2 = p2[2], t3 = p2[3];
            ull e[8], o[7];
            e[0] = pack2(t0.x, t0.y); e[1] = pack2(t0.z, t0.w);
            e[2] = pack2(t1.x, t1.y); e[3] = pack2(t1.z, t1.w);
            e[4] = pack2(t2.x, t2.y); e[5] = pack2(t2.z, t2.w);
            e[6] = pack2(t3.x, t3.y); e[7] = pack2(t3.z, t3.w);
            o[0] = pack2(t0.y, t0.z); o[1] = pack2(t0.w, t1.x);
            o[2] = pack2(t1.y, t1.z); o[3] = pack2(t1.w, t2.x);
            o[4] = pack2(t2.y, t2.z); o[5] = pack2(t2.w, t3.x);
            o[6] = pack2(t3.y, t3.z);

            #pragma unroll
            for (int xp = 0; xp < 4; xp++) {
                #pragma unroll
                for (int j = 0; j < 9; j++) {
                    ull tp = (j & 1) ? o[xp + ((j-1)>>1)] : e[xp + (j>>1)];
                    fma2(acc[xp][j], vp[xp], tp);
                }
            }
        }

        if (cc == 7) {
            const ull scc = pack2(1.0f/64.0f, 1.0f/64.0f);
            long obase = ((long)(b*NIDX + k*81 + i*9) * HW
                          + (long)y*W_ + xb + lx0) * DD + z;
            #pragma unroll
            for (int xp = 0; xp < 4; xp++) {
                #pragma unroll
                for (int j = 0; j < 9; j++) {
                    float s0f, s1f; unpack2(mul2(acc[xp][j], scc), s0f, s1f);
                    out[obase + (long)j*HWD + (2*xp  )*DD] = s0f;
                    out[obase + (long)j*HWD + (2*xp+1)*DD] = s1f;
                }
            }
            const int yr = y + i - 4;
            const bool vrow = (yr >= 0) && (yr < H_);
            float m2w[16];
            #pragma unroll
            for (int n = 0; n < 16; n++) {
                int gxr = xb + lx0 - 4 + n;
                m2w[n] = (vrow && gxr >= 0 && gxr < W_)
                           ? __ldg(g_m2 + b*HW + yr*W_ + gxr) : 1.0f;
            }
            #pragma unroll
            for (int xi = 0; xi < PT; xi++) {
                #pragma unroll
                for (int j = 0; j < 9; j++) {
                    float mv = zedge ? m1x[xi] : (m1x[xi] * m2w[xi + j]);
                    omask[obase + (long)j*HWD + xi*DD] = mv;
                }
            }
        }
    }
}

// ---------------------------------------------------------------------------
__global__ void mask_sum_kernel(const float* __restrict__ a1,
                                const float* __restrict__ a2) {
    int n = blockIdx.x * blockDim.x + threadIdx.x;
    if (n >= B_*HW) return;
    const float4* p1 = (const float4*)(a1 + (size_t)n * DD);
    const float4* p2 = (const float4*)(a2 + (size_t)n * DD);
    float4 u = p1[0], v = p1[1];
    float s1 = u.x+u.y+u.z+u.w + v.x+v.y+v.z+v.w;
    u = p2[0]; v = p2[1];
    float s2 = u.x+u.y+u.z+u.w + v.x+v.y+v.z+v.w;
    g_m1[n] = fminf(fmaxf(s1, 0.f), 1.f);
    g_m2[n] = fminf(fmaxf(s2, 0.f), 1.f);
}

// ---------------------------------------------------------------------------
extern "C" void kernel_launch(void* const* d_in, const int* in_sizes, int n_in,
                              void* d_out, int out_size) {
    const float* f1 = (const float*)d_in[0];
    const float* a1 = (const float*)d_in[1];
    const float* f2 = (const float*)d_in[2];
    const float* a2 = (const float*)d_in[3];
    float* out      = (float*)d_out;
    float* out_mask = out + (long)B_ * NIDX * HWD;

    mask_sum_kernel<<<(B_*HW + 255) / 256, 256>>>(a1, a2);

    dim3 g(W_ / PX, H_, B_);
    cost_kernel<<<g, 128, SMEM_BYTES>>>(f1, f2, out, out_mask);
}

// round 6
// speedup vs baseline: 1.5019x; 1.5019x over previous
#include <cuda_runtime.h>

typedef unsigned long long ull;

#define B_   4
#define C_   64
#define H_   96
#define W_   96
#define DD   8
#define HW   (H_*W_)          // 9216
#define HWD  (H_*W_*DD)       // 73728
#define NIDX 243

#define PX   32
#define PT   8
#define CCH  8
#define NST  72      // 9 i-shifts * 8 channel chunks
#define F1COL 36     // stride/4 odd -> perfect 4-phase LDS.128
#define F2COL 44
#define F1W  (CCH*8*F1COL)     // 2304 words
#define F2W  (CCH*10*F2COL)    // 3520 words
#define SMEM_WORDS (2*F1W + 2*F2W)
#define SMEM_BYTES (SMEM_WORDS*4)   // 46592 B -> 4 blocks/SM

__device__ float g_m1[B_*HW];
__device__ float g_m2[B_*HW];

__device__ __forceinline__ void fma2(ull &d, ull a, ull b) {
    asm("fma.rn.f32x2 %0, %1, %2, %0;" : "+l"(d) : "l"(a), "l"(b));
}
__device__ __forceinline__ ull mul2(ull a, ull b) {
    ull d; asm("mul.rn.f32x2 %0, %1, %2;" : "=l"(d) : "l"(a), "l"(b)); return d;
}
__device__ __forceinline__ ull pack2(float lo, float hi) {
    ull r; asm("mov.b64 %0, {%1, %2};" : "=l"(r) : "f"(lo), "f"(hi)); return r;
}
__device__ __forceinline__ void unpack2(ull v, float &lo, float &hi) {
    asm("mov.b64 {%0, %1}, %2;" : "=f"(lo), "=f"(hi) : "l"(v));
}

// compute 4 channels' worth of correlation on current buffers
__device__ __forceinline__ void compute4(
    const float* __restrict__ f1s, const float* __restrict__ f2s,
    int clbase, int z, int zi, int lx0, ull acc[4][9])
{
    #pragma unroll
    for (int cu = 0; cu < 4; cu++) {
        const int cl = clbase + cu;
        const float4* p1 = (const float4*)(f1s + (cl*8 + z)*F1COL + lx0);
        float4 va = p1[0], vb = p1[1];
        ull vp[4];
        vp[0] = pack2(va.x, va.y); vp[1] = pack2(va.z, va.w);
        vp[2] = pack2(vb.x, vb.y); vp[3] = pack2(vb.z, vb.w);

        const float4* p2 = (const float4*)(f2s + (cl*10 + zi)*F2COL + lx0);
        float4 t0 = p2[0], t1 = p2[1], t2 = p2[2], t3 = p2[3];
        ull e[8], o[7];
        e[0] = pack2(t0.x, t0.y); e[1] = pack2(t0.z, t0.w);
        e[2] = pack2(t1.x, t1.y); e[3] = pack2(t1.z, t1.w);
        e[4] = pack2(t2.x, t2.y); e[5] = pack2(t2.z, t2.w);
        e[6] = pack2(t3.x, t3.y); e[7] = pack2(t3.z, t3.w);
        o[0] = pack2(t0.y, t0.z); o[1] = pack2(t0.w, t1.x);
        o[2] = pack2(t1.y, t1.z); o[3] = pack2(t1.w, t2.x);
        o[4] = pack2(t2.y, t2.z); o[5] = pack2(t2.w, t3.x);
        o[6] = pack2(t3.y, t3.z);

        #pragma unroll
        for (int xp = 0; xp < 4; xp++) {
            #pragma unroll
            for (int j = 0; j < 9; j++) {
                ull tp = (j & 1) ? o[xp + ((j-1)>>1)] : e[xp + (j>>1)];
                fma2(acc[xp][j], vp[xp], tp);
            }
        }
    }
}

// ---------------------------------------------------------------------------
// Cost + fused mask kernel, register-staged fill pipeline.
// 96 threads: txg(4, 8px) x z(8) x k(3). Per stage:
//   sync -> LDG f2-next (regs) -> compute cl0-3 -> STS f2-next
//        -> LDG f1-next (regs) -> compute cl4-7 -> STS f1-next
// LDG latency hidden behind compute; no warp ever stalls at a fill STS.
// ---------------------------------------------------------------------------
__global__ void __launch_bounds__(96, 4)
cost_kernel(const float* __restrict__ f1g, const float* __restrict__ f2g,
            float* __restrict__ out, float* __restrict__ omask)
{
    extern __shared__ float sm[];
    float* f1b0 = sm;
    float* f1b1 = sm + F1W;
    float* f2b0 = sm + 2*F1W;
    float* f2b1 = sm + 2*F1W + F2W;

    const int tid = threadIdx.x;
    const int txg = tid & 3;
    const int z   = (tid >> 2) & 7;
    const int k   = tid >> 5;
    const int lx0 = txg * PT;
    const int xb  = blockIdx.x * PX;
    const int y   = blockIdx.y;
    const int b   = blockIdx.z;
    const int zi  = z + k;

    // ---- per-thread f2 fill descriptors (7 slots, idx = tid + 96*it)
    int  f2off[7], f2wb[7];
    bool f2ok[7];
    #pragma unroll
    for (int it = 0; it < 7; it++) {
        int idx = tid + it*96;
        int cl  = idx / 84;
        int r   = idx - cl*84;
        int col = r >> 1;
        int q   = r & 1;
        int gx  = xb - 4 + col;
        f2ok[it]  = (gx >= 0) && (gx < W_);
        f2off[it] = cl*HWD + gx*DD + q*4;
        f2wb[it]  = (cl*10 + 1 + q*4)*F2COL + col;
    }

    // zero the z-pad planes of both f2 buffers
    for (int n = tid; n < 2*CCH*2*F2COL; n += 96) {
        int p   = n / (CCH*2*F2COL);
        int r   = n - p*(CCH*2*F2COL);
        int cl  = r / (2*F2COL);
        int r2  = r - cl*(2*F2COL);
        int zp  = (r2 >= F2COL) ? 9 : 0;
        int col = (r2 >= F2COL) ? (r2 - F2COL) : r2;
        (p ? f2b1 : f2b0)[(cl*10 + zp)*F2COL + col] = 0.f;
    }

    float m1x[PT];
    {
        const float* m1p = g_m1 + b*HW + y*W_ + xb + lx0;
        float4 a = *(const float4*)(m1p);
        float4 c = *(const float4*)(m1p + 4);
        m1x[0]=a.x; m1x[1]=a.y; m1x[2]=a.z; m1x[3]=a.w;
        m1x[4]=c.x; m1x[5]=c.y; m1x[6]=c.z; m1x[7]=c.w;
    }
    const bool zedge = (zi == 0) || (zi == 9);

    // ---- prologue: fill stage 0 (i=0, cc=0). yr0 = y-4: valid when y>=4.
    {
        const float* s1 = f1g + ((size_t)(b*C_))*HWD + ((size_t)y*W_ + xb)*DD;
        #pragma unroll
        for (int it = 0; it < 6; it++) {
            int idx = tid + it*96;
            if (idx < 512) {
                int c = idx >> 6, r = idx & 63, col = r >> 1, q = r & 1;
                float4 v = *(const float4*)(s1 + (size_t)c*HWD + col*DD + q*4);
                int wb = (c*8 + q*4)*F1COL + col;
                f1b0[wb]=v.x; f1b0[wb+F1COL]=v.y; f1b0[wb+2*F1COL]=v.z; f1b0[wb+3*F1COL]=v.w;
            }
        }
        const int  yr0   = y - 4;
        const bool vrow0 = (yr0 >= 0);             // yr0 < H_ always (y < 96)
        const float* s2 = f2g + ((size_t)(b*C_))*HWD
                          + (size_t)(vrow0 ? yr0 : 0) * (W_*DD);
        #pragma unroll
        for (int it = 0; it < 7; it++) {
            float4 v = make_float4(0.f,0.f,0.f,0.f);
            if (vrow0 && f2ok[it]) v = *(const float4*)(s2 + f2off[it]);
            int wb = f2wb[it];
            f2b0[wb]=v.x; f2b0[wb+F2COL]=v.y; f2b0[wb+2*F2COL]=v.z; f2b0[wb+3*F2COL]=v.w;
        }
    }

    ull acc[4][9];

    for (int s = 0; s < NST; s++) {
        const int par = s & 1;
        __syncthreads();   // buf[par] filled; prior use of buf[par^1] done

        const float* f1s = par ? f1b1 : f1b0;
        const float* f2s = par ? f2b1 : f2b0;
        float* f1d = par ? f1b0 : f1b1;
        float* f2d = par ? f2b0 : f2b1;

        const int i  = s >> 3;
        const int cc = s & 7;

        // next-stage fill parameters
        const int  sn    = s + 1;
        const bool hasn  = sn < NST;
        const int  in_   = sn >> 3;
        const int  ccn   = sn & 7;
        const int  yrn   = y + in_ - 4;
        const bool vrown = hasn && (yrn >= 0) && (yrn < H_);

        // ---- phase 1: LDG f2-next into registers
        float4 Bv[7];
        {
            const float* s2 = f2g + ((size_t)(b*C_ + ccn*CCH))*HWD
                              + (size_t)(vrown ? yrn : 0) * (W_*DD);
            #pragma unroll
            for (int it = 0; it < 7; it++) {
                float4 v = make_float4(0.f,0.f,0.f,0.f);
                if (vrown && f2ok[it]) v = *(const float4*)(s2 + f2off[it]);
                Bv[it] = v;
            }
        }

        if (cc == 0) {
            #pragma unroll
            for (int xp = 0; xp < 4; xp++)
                #pragma unroll
                for (int j = 0; j < 9; j++) acc[xp][j] = 0ull;
        }

        // ---- phase 2: compute channels 0-3 (covers f2 LDG latency)
        compute4(f1s, f2s, 0, z, zi, lx0, acc);

        // ---- phase 3: STS f2-next
        if (hasn) {
            #pragma unroll
            for (int it = 0; it < 7; it++) {
                int wb = f2wb[it];
                f2d[wb]=Bv[it].x; f2d[wb+F2COL]=Bv[it].y;
                f2d[wb+2*F2COL]=Bv[it].z; f2d[wb+3*F2COL]=Bv[it].w;
            }
        }

        // ---- phase 4: LDG f1-next into registers
        float4 Av[6];
        {
            const float* s1 = f1g + ((size_t)(b*C_ + ccn*CCH))*HWD
                              + ((size_t)y*W_ + xb)*DD;
            #pragma unroll
            for (int it = 0; it < 6; it++) {
                int idx = tid + it*96;
                float4 v = make_float4(0.f,0.f,0.f,0.f);
                if (hasn && idx < 512) {
                    int c = idx >> 6, r = idx & 63, col = r >> 1, q = r & 1;
                    v = *(const float4*)(s1 + (size_t)c*HWD + col*DD + q*4);
                }
                Av[it] = v;
            }
        }

        // ---- phase 5: compute channels 4-7 (covers f1 LDG latency)
        compute4(f1s, f2s, 4, z, zi, lx0, acc);

        // ---- phase 6: STS f1-next
        if (hasn) {
            #pragma unroll
            for (int it = 0; it < 6; it++) {
                int idx = tid + it*96;
                if (idx < 512) {
                    int c = idx >> 6, r = idx & 63, col = r >> 1, q = r & 1;
                    int wb = (c*8 + q*4)*F1COL + col;
                    f1d[wb]=Av[it].x; f1d[wb+F1COL]=Av[it].y;
                    f1d[wb+2*F1COL]=Av[it].z; f1d[wb+3*F1COL]=Av[it].w;
                }
            }
        }

        // ---- outputs at end of each i-group
        if (cc == 7) {
            const ull scc = pack2(1.0f/64.0f, 1.0f/64.0f);
            long obase = ((long)(b*NIDX + k*81 + i*9) * HW
                          + (long)y*W_ + xb + lx0) * DD + z;
            #pragma unroll
            for (int xp = 0; xp < 4; xp++) {
                #pragma unroll
                for (int j = 0; j < 9; j++) {
                    float s0f, s1f; unpack2(mul2(acc[xp][j], scc), s0f, s1f);
                    out[obase + (long)j*HWD + (2*xp  )*DD] = s0f;
                    out[obase + (long)j*HWD + (2*xp+1)*DD] = s1f;
                }
            }
            const int yr = y + i - 4;
            const bool vrow = (yr >= 0) && (yr < H_);
            float m2w[16];
            #pragma unroll
            for (int n = 0; n < 16; n++) {
                int gxr = xb + lx0 - 4 + n;
                m2w[n] = (vrow && gxr >= 0 && gxr < W_)
                           ? __ldg(g_m2 + b*HW + yr*W_ + gxr) : 1.0f;
            }
            #pragma unroll
            for (int xi = 0; xi < PT; xi++) {
                #pragma unroll
                for (int j = 0; j < 9; j++) {
                    float mv = zedge ? m1x[xi] : (m1x[xi] * m2w[xi + j]);
                    omask[obase + (long)j*HWD + xi*DD] = mv;
                }
            }
        }
    }
}

// ---------------------------------------------------------------------------
__global__ void mask_sum_kernel(const float* __restrict__ a1,
                                const float* __restrict__ a2) {
    int n = blockIdx.x * blockDim.x + threadIdx.x;
    if (n >= B_*HW) return;
    const float4* p1 = (const float4*)(a1 + (size_t)n * DD);
    const float4* p2 = (const float4*)(a2 + (size_t)n * DD);
    float4 u = p1[0], v = p1[1];
    float s1 = u.x+u.y+u.z+u.w + v.x+v.y+v.z+v.w;
    u = p2[0]; v = p2[1];
    float s2 = u.x+u.y+u.z+u.w + v.x+v.y+v.z+v.w;
    g_m1[n] = fminf(fmaxf(s1, 0.f), 1.f);
    g_m2[n] = fminf(fmaxf(s2, 0.f), 1.f);
}

// ---------------------------------------------------------------------------
extern "C" void kernel_launch(void* const* d_in, const int* in_sizes, int n_in,
                              void* d_out, int out_size) {
    const float* f1 = (const float*)d_in[0];
    const float* a1 = (const float*)d_in[1];
    const float* f2 = (const float*)d_in[2];
    const float* a2 = (const float*)d_in[3];
    float* out      = (float*)d_out;
    float* out_mask = out + (long)B_ * NIDX * HWD;

    mask_sum_kernel<<<(B_*HW + 255) / 256, 256>>>(a1, a2);

    dim3 g(W_ / PX, H_, B_);
    cost_kernel<<<g, 96, SMEM_BYTES>>>(f1, f2, out, out_mask);
}